// round 16
// baseline (speedup 1.0000x reference)
#include <cuda_runtime.h>
#include <cuda_fp16.h>
#include <mma.h>
#include <cstdint>

using namespace nvcuda;

#define MAX_NODES 100000
#define MAX_EDGES 1600000
#define D 128

// ---------------------------------------------------------------------------
// Scratch (__device__ globals: allocation-free rule)
// A_cat[node][256] fp16: cols 0..127 = mean agg, cols 128..255 = x row.
// ---------------------------------------------------------------------------
__device__ __align__(16) __half g_Acat[(size_t)MAX_NODES * 256];
__device__ __align__(16) __half g_Wh[128 * 256];   // [out-col][k] fp16
__device__ int g_count[MAX_NODES];
__device__ int g_rowptr[MAX_NODES + 1];
__device__ int g_cursor[MAX_NODES];
__device__ int g_csr_src[MAX_EDGES];
__device__ int g_is64;

// ---------------------------------------------------------------------------
// Phase 0 (merged setup): detect dtype + zero counters + xconv + wconv.
// ---------------------------------------------------------------------------
#define XB ((MAX_NODES * 16 + 255) / 256)          // 6250
#define WB ((128 * 256 + 255) / 256)               // 128
#define IB ((MAX_NODES + 255) / 256)               // 391
#define SETUP_BLOCKS (XB + WB + IB + 1)

__global__ void setup_kernel(const float* __restrict__ x,
                             const float* __restrict__ Wl,
                             const float* __restrict__ Wr,
                             const int* __restrict__ ei32,
                             int N) {
    int b = blockIdx.x;
    if (b < XB) {
        int t = b * 256 + threadIdx.x;            // one per 8 elems
        int total8 = N * (D / 8);
        if (t >= total8) return;
        int node = t >> 4;
        int g = t & 15;
        const float4* p = reinterpret_cast<const float4*>(x + (size_t)node * D + g * 8);
        float4 a = __ldg(p), bb = __ldg(p + 1);
        __half2 h0 = __floats2half2_rn(a.x, a.y);
        __half2 h1 = __floats2half2_rn(a.z, a.w);
        __half2 h2 = __floats2half2_rn(bb.x, bb.y);
        __half2 h3 = __floats2half2_rn(bb.z, bb.w);
        uint4 ov;
        ov.x = *reinterpret_cast<uint32_t*>(&h0);
        ov.y = *reinterpret_cast<uint32_t*>(&h1);
        ov.z = *reinterpret_cast<uint32_t*>(&h2);
        ov.w = *reinterpret_cast<uint32_t*>(&h3);
        *reinterpret_cast<uint4*>(g_Acat + (size_t)node * 256 + 128 + g * 8) = ov;
    } else if (b < XB + WB) {
        int t = (b - XB) * 256 + threadIdx.x;
        if (t >= 128 * 256) return;
        int o = t >> 8, k = t & 255;
        float w = (k < 128) ? Wl[o * 128 + k] : Wr[o * 128 + (k - 128)];
        g_Wh[t] = __float2half_rn(w);
    } else if (b < XB + WB + IB) {
        int t = (b - XB - WB) * 256 + threadIdx.x;
        if (t < N) g_count[t] = 0;
    } else {
        if (threadIdx.x == 0) {
            int nz = 0;
#pragma unroll 1
            for (int i = 0; i < 64; i++) nz |= ei32[2 * i + 1];
            g_is64 = (nz == 0) ? 1 : 0;
        }
    }
}

// Phase 1: degree histogram, 4 edges per thread (int4 loads)
__global__ void hist_kernel(const int* __restrict__ ei32, int E) {
    int e = (blockIdx.x * blockDim.x + threadIdx.x) * 4;
    if (e >= E) return;
    int d[4];
    int n = (E - e < 4) ? (E - e) : 4;
    if (g_is64) {
        const int4* p = reinterpret_cast<const int4*>(ei32 + 2 * (E + e));
        int4 v0 = __ldg(p);
        d[0] = v0.x; d[1] = v0.z;
        if (n > 2) {
            int4 v1 = __ldg(p + 1);
            d[2] = v1.x; d[3] = v1.z;
        }
    } else {
        const int4* p = reinterpret_cast<const int4*>(ei32 + E + e);
        int4 v = __ldg(p);
        d[0] = v.x; d[1] = v.y; d[2] = v.z; d[3] = v.w;
    }
#pragma unroll
    for (int i = 0; i < 4; i++)
        if (i < n) atomicAdd(&g_count[d[i]], 1);
}

// ---------------------------------------------------------------------------
// Phase 2: single-block exclusive scan (1024 threads x 98 elements).
// Pass 1: per-thread segment sum. Kogge-Stone over 1024 partials.
// Pass 2: re-read counts (L2-hot), write rowptr + cursor.
// ---------------------------------------------------------------------------
#define SCAN_PER ((MAX_NODES + 1023) / 1024)   // 98

__global__ __launch_bounds__(1024) void scan_kernel(int N, int E) {
    __shared__ int sh[1024];
    int t = threadIdx.x;
    int base = t * SCAN_PER;
    int s = 0;
#pragma unroll 1
    for (int i = 0; i < SCAN_PER; i++) {
        int idx = base + i;
        if (idx < N) s += g_count[idx];
    }
    sh[t] = s;
    __syncthreads();
    for (int off = 1; off < 1024; off <<= 1) {
        int xv = (t >= off) ? sh[t - off] : 0;
        __syncthreads();
        sh[t] += xv;
        __syncthreads();
    }
    int run = sh[t] - s;   // exclusive prefix of this thread's segment
#pragma unroll 1
    for (int i = 0; i < SCAN_PER; i++) {
        int idx = base + i;
        if (idx < N) {
            int c = g_count[idx];
            g_rowptr[idx] = run;
            g_cursor[idx] = run;
            run += c;
        }
    }
    if (t == 0) g_rowptr[N] = E;
}

// Phase 3: fill CSR src lists, 4 edges per thread (int4 loads)
__global__ void fill_kernel(const int* __restrict__ ei32, int E) {
    int e = (blockIdx.x * blockDim.x + threadIdx.x) * 4;
    if (e >= E) return;
    int s[4], d[4];
    int n = (E - e < 4) ? (E - e) : 4;
    if (g_is64) {
        const int4* sp = reinterpret_cast<const int4*>(ei32 + 2 * e);
        const int4* dp = reinterpret_cast<const int4*>(ei32 + 2 * (E + e));
        int4 sv0 = __ldg(sp), dv0 = __ldg(dp);
        s[0] = sv0.x; s[1] = sv0.z; d[0] = dv0.x; d[1] = dv0.z;
        if (n > 2) {
            int4 sv1 = __ldg(sp + 1), dv1 = __ldg(dp + 1);
            s[2] = sv1.x; s[3] = sv1.z; d[2] = dv1.x; d[3] = dv1.z;
        }
    } else {
        int4 sv = __ldg(reinterpret_cast<const int4*>(ei32 + e));
        int4 dv = __ldg(reinterpret_cast<const int4*>(ei32 + E + e));
        s[0] = sv.x; s[1] = sv.y; s[2] = sv.z; s[3] = sv.w;
        d[0] = dv.x; d[1] = dv.y; d[2] = dv.z; d[3] = dv.w;
    }
#pragma unroll
    for (int i = 0; i < 4; i++) {
        if (i < n) {
            int pos = atomicAdd(&g_cursor[d[i]], 1);
            g_csr_src[pos] = s[i];
        }
    }
}

// ---------------------------------------------------------------------------
// Phase 4: gather-aggregate (mean). TWO nodes per warp: each 16-lane half
// owns one node; lane owns uint4 = 8 halves (16 lanes x 16B = 256B row).
// Doubles in-flight loads per warp on this latency-bound gather.
// fp32 accumulation; fp16 mean written to A_cat cols 0..127.
// ---------------------------------------------------------------------------
__global__ __launch_bounds__(256) void agg_kernel(int N) {
    int warp = (blockIdx.x * blockDim.x + threadIdx.x) >> 5;
    int lane = threadIdx.x & 31;
    int half = lane >> 4;
    int l16 = lane & 15;
    int w = warp * 2 + half;
    if (w >= N) return;
    int beg = g_rowptr[w];
    int end = g_rowptr[w + 1];
    const uint4* xb = reinterpret_cast<const uint4*>(g_Acat);  // 8 halves per uint4
    // src row s cols 128..255 -> uint4 index s*32 + 16 + l16
    float acc[8];
#pragma unroll
    for (int i = 0; i < 8; i++) acc[i] = 0.f;

    int e = beg;
    while (e + 3 < end) {
        int s0 = g_csr_src[e];
        int s1 = g_csr_src[e + 1];
        int s2 = g_csr_src[e + 2];
        int s3 = g_csr_src[e + 3];
        uint4 a = __ldg(xb + (size_t)s0 * 32 + 16 + l16);
        uint4 b = __ldg(xb + (size_t)s1 * 32 + 16 + l16);
        uint4 c = __ldg(xb + (size_t)s2 * 32 + 16 + l16);
        uint4 d = __ldg(xb + (size_t)s3 * 32 + 16 + l16);
#pragma unroll
        for (int q = 0; q < 4; q++) {
            uint4 v = (q == 0) ? a : (q == 1) ? b : (q == 2) ? c : d;
            float2 f0 = __half22float2(*reinterpret_cast<__half2*>(&v.x));
            float2 f1 = __half22float2(*reinterpret_cast<__half2*>(&v.y));
            float2 f2 = __half22float2(*reinterpret_cast<__half2*>(&v.z));
            float2 f3 = __half22float2(*reinterpret_cast<__half2*>(&v.w));
            acc[0] += f0.x; acc[1] += f0.y; acc[2] += f1.x; acc[3] += f1.y;
            acc[4] += f2.x; acc[5] += f2.y; acc[6] += f3.x; acc[7] += f3.y;
        }
        e += 4;
    }
    while (e < end) {
        int s = g_csr_src[e];
        uint4 v = __ldg(xb + (size_t)s * 32 + 16 + l16);
        float2 f0 = __half22float2(*reinterpret_cast<__half2*>(&v.x));
        float2 f1 = __half22float2(*reinterpret_cast<__half2*>(&v.y));
        float2 f2 = __half22float2(*reinterpret_cast<__half2*>(&v.z));
        float2 f3 = __half22float2(*reinterpret_cast<__half2*>(&v.w));
        acc[0] += f0.x; acc[1] += f0.y; acc[2] += f1.x; acc[3] += f1.y;
        acc[4] += f2.x; acc[5] += f2.y; acc[6] += f3.x; acc[7] += f3.y;
        e++;
    }
    float inv = 1.0f / fmaxf((float)(end - beg), 1.0f);
    __half2 m0 = __floats2half2_rn(acc[0] * inv, acc[1] * inv);
    __half2 m1 = __floats2half2_rn(acc[2] * inv, acc[3] * inv);
    __half2 m2 = __floats2half2_rn(acc[4] * inv, acc[5] * inv);
    __half2 m3 = __floats2half2_rn(acc[6] * inv, acc[7] * inv);
    uint4 o;
    o.x = *reinterpret_cast<uint32_t*>(&m0);
    o.y = *reinterpret_cast<uint32_t*>(&m1);
    o.z = *reinterpret_cast<uint32_t*>(&m2);
    o.w = *reinterpret_cast<uint32_t*>(&m3);
    *(reinterpret_cast<uint4*>(g_Acat) + (size_t)w * 32 + l16) = o;  // cols 0..127
}

// ---------------------------------------------------------------------------
// Phase 5: single-pass fp16 WMMA GEMM.
//   out[128n x 128o] = Acat[128 x 256] * Wcat^T + bias  (fp32 accum)
// CTA 128x128, 256 threads = 8 warps, warp tile 32x64 (2x4 frags).
// K chunks of 32, smem stride 40 halves. Pure uint4 staging.
// ---------------------------------------------------------------------------
#define ASTR 40

__global__ __launch_bounds__(256, 2) void gemm_fp16_kernel(
    const float* __restrict__ bl,
    float* __restrict__ out,
    int N) {
    __shared__ __align__(16) __half a_s[128 * ASTR];
    __shared__ __align__(16) __half w_s[128 * ASTR];
    __shared__ __align__(16) float bias_s[16 * 128];

    const int tid = threadIdx.x;
    const int wid = tid >> 5;
    const int node0 = blockIdx.x * 128;
    const int wr = (wid & 3) * 32;   // warp row offset
    const int wc = (wid >> 2) * 64;  // warp col offset

    // bias tile: 16 identical rows of bl[0..127]
    {
        float bv = __ldg(bl + (tid & 127));
        int r0 = tid >> 7;
#pragma unroll
        for (int r = 0; r < 16; r += 2)
            bias_s[(r + r0) * 128 + (tid & 127)] = bv;
    }
    __syncthreads();

    wmma::fragment<wmma::accumulator, 16, 16, 16, float> acc[2][4];
#pragma unroll
    for (int i = 0; i < 2; i++)
#pragma unroll
        for (int j = 0; j < 4; j++)
            wmma::load_matrix_sync(acc[i][j], &bias_s[wc + j * 16], 128, wmma::mem_row_major);

    const int row = tid >> 1;         // 0..127 (node row AND W out-col)
    const int seg = (tid & 1) * 16;   // 16-half segment of the 32-col chunk
    const int gn  = node0 + row;
    const bool va = (gn < N);

#pragma unroll 1
    for (int c = 0; c < 8; c++) {
        __syncthreads();
        // ---- stage A chunk: pure fp16 uint4 copies ----
        {
            uint4 v0, v1;
            if (va) {
                const uint4* p = reinterpret_cast<const uint4*>(g_Acat + (size_t)gn * 256 + c * 32 + seg);
                v0 = __ldg(p); v1 = __ldg(p + 1);
            } else {
                v0 = v1 = make_uint4(0, 0, 0, 0);
            }
            uint4* dst = reinterpret_cast<uint4*>(&a_s[row * ASTR + seg]);
            dst[0] = v0; dst[1] = v1;
        }
        // ---- stage W chunk ----
        {
            const uint4* p = reinterpret_cast<const uint4*>(g_Wh + row * 256 + c * 32 + seg);
            uint4* dst = reinterpret_cast<uint4*>(&w_s[row * ASTR + seg]);
            dst[0] = __ldg(p); dst[1] = __ldg(p + 1);
        }
        __syncthreads();

        // ---- compute: 2 k-steps x 2 row frags x 4 col frags ----
#pragma unroll
        for (int ks = 0; ks < 2; ks++) {
            wmma::fragment<wmma::matrix_a, 16, 16, 16, __half, wmma::row_major> af[2];
            wmma::fragment<wmma::matrix_b, 16, 16, 16, __half, wmma::col_major> bf[4];
#pragma unroll
            for (int i = 0; i < 2; i++)
                wmma::load_matrix_sync(af[i], &a_s[(wr + i * 16) * ASTR + ks * 16], ASTR);
#pragma unroll
            for (int j = 0; j < 4; j++)
                wmma::load_matrix_sync(bf[j], &w_s[(wc + j * 16) * ASTR + ks * 16], ASTR);
#pragma unroll
            for (int i = 0; i < 2; i++)
#pragma unroll
                for (int j = 0; j < 4; j++)
                    wmma::mma_sync(acc[i][j], af[i], bf[j], acc[i][j]);
        }
    }

    // ---- epilogue: direct fragment stores (bias already in acc) ----
#pragma unroll
    for (int i = 0; i < 2; i++) {
        int r0 = node0 + wr + i * 16;
        if (r0 < N) {  // N % 16 == 0 -> frag fully valid
#pragma unroll
            for (int j = 0; j < 4; j++)
                wmma::store_matrix_sync(out + (size_t)r0 * D + wc + j * 16, acc[i][j], D, wmma::mem_row_major);
        }
    }
}

// ---------------------------------------------------------------------------
extern "C" void kernel_launch(void* const* d_in, const int* in_sizes, int n_in,
                              void* d_out, int out_size) {
    const float* x    = (const float*)d_in[0];
    const int*   ei32 = (const int*)d_in[1];
    const float* Wl   = (const float*)d_in[2];
    const float* bl   = (const float*)d_in[3];
    const float* Wr   = (const float*)d_in[4];
    float*       out  = (float*)d_out;

    int N = in_sizes[0] / D;       // 100000
    int E = in_sizes[1] / 2;       // 1600000

    setup_kernel<<<SETUP_BLOCKS, 256>>>(x, Wl, Wr, ei32, N);
    hist_kernel<<<(E / 4 + 255) / 256, 256>>>(ei32, E);
    scan_kernel<<<1, 1024>>>(N, E);
    fill_kernel<<<(E / 4 + 255) / 256, 256>>>(ei32, E);
    {
        int warps = (N + 1) / 2;
        agg_kernel<<<(warps * 32 + 255) / 256, 256>>>(N);
    }
    gemm_fp16_kernel<<<(N + 127) / 128, 256>>>(bl, out, N);
}

// round 17
// speedup vs baseline: 1.4684x; 1.4684x over previous
#include <cuda_runtime.h>
#include <cuda_fp16.h>
#include <mma.h>
#include <cstdint>

using namespace nvcuda;

#define MAX_NODES 100000
#define MAX_EDGES 1600000
#define D 128

// ---------------------------------------------------------------------------
// Scratch (__device__ globals: allocation-free rule)
// A_cat[node][256] fp16: cols 0..127 = mean agg, cols 128..255 = x row.
// ---------------------------------------------------------------------------
__device__ __align__(16) __half g_Acat[(size_t)MAX_NODES * 256];
__device__ __align__(16) __half g_Wh[128 * 256];   // [out-col][k] fp16
__device__ int g_count[MAX_NODES];
__device__ int g_rowptr[MAX_NODES + 1];
__device__ int g_cursor[MAX_NODES];
__device__ int g_csr_src[MAX_EDGES];
__device__ int g_is64;

// ---------------------------------------------------------------------------
// Phase 0 (merged setup): detect dtype + zero counters + xconv + wconv.
// ---------------------------------------------------------------------------
#define XB ((MAX_NODES * 16 + 255) / 256)          // 6250
#define WB ((128 * 256 + 255) / 256)               // 128
#define IB ((MAX_NODES + 255) / 256)               // 391
#define SETUP_BLOCKS (XB + WB + IB + 1)

__global__ void setup_kernel(const float* __restrict__ x,
                             const float* __restrict__ Wl,
                             const float* __restrict__ Wr,
                             const int* __restrict__ ei32,
                             int N) {
    int b = blockIdx.x;
    if (b < XB) {
        int t = b * 256 + threadIdx.x;            // one per 8 elems
        int total8 = N * (D / 8);
        if (t >= total8) return;
        int node = t >> 4;
        int g = t & 15;
        const float4* p = reinterpret_cast<const float4*>(x + (size_t)node * D + g * 8);
        float4 a = __ldg(p), bb = __ldg(p + 1);
        __half2 h0 = __floats2half2_rn(a.x, a.y);
        __half2 h1 = __floats2half2_rn(a.z, a.w);
        __half2 h2 = __floats2half2_rn(bb.x, bb.y);
        __half2 h3 = __floats2half2_rn(bb.z, bb.w);
        uint4 ov;
        ov.x = *reinterpret_cast<uint32_t*>(&h0);
        ov.y = *reinterpret_cast<uint32_t*>(&h1);
        ov.z = *reinterpret_cast<uint32_t*>(&h2);
        ov.w = *reinterpret_cast<uint32_t*>(&h3);
        *reinterpret_cast<uint4*>(g_Acat + (size_t)node * 256 + 128 + g * 8) = ov;
    } else if (b < XB + WB) {
        int t = (b - XB) * 256 + threadIdx.x;
        if (t >= 128 * 256) return;
        int o = t >> 8, k = t & 255;
        float w = (k < 128) ? Wl[o * 128 + k] : Wr[o * 128 + (k - 128)];
        g_Wh[t] = __float2half_rn(w);
    } else if (b < XB + WB + IB) {
        int t = (b - XB - WB) * 256 + threadIdx.x;
        if (t < N) g_count[t] = 0;
    } else {
        if (threadIdx.x == 0) {
            int nz = 0;
#pragma unroll 1
            for (int i = 0; i < 64; i++) nz |= ei32[2 * i + 1];
            g_is64 = (nz == 0) ? 1 : 0;
        }
    }
}

// Phase 1: degree histogram, 4 edges per thread (int4 loads)
__global__ void hist_kernel(const int* __restrict__ ei32, int E) {
    int e = (blockIdx.x * blockDim.x + threadIdx.x) * 4;
    if (e >= E) return;
    int d[4];
    int n = (E - e < 4) ? (E - e) : 4;
    if (g_is64) {
        const int4* p = reinterpret_cast<const int4*>(ei32 + 2 * (E + e));
        int4 v0 = __ldg(p);
        d[0] = v0.x; d[1] = v0.z;
        if (n > 2) {
            int4 v1 = __ldg(p + 1);
            d[2] = v1.x; d[3] = v1.z;
        }
    } else {
        const int4* p = reinterpret_cast<const int4*>(ei32 + E + e);
        int4 v = __ldg(p);
        d[0] = v.x; d[1] = v.y; d[2] = v.z; d[3] = v.w;
    }
#pragma unroll
    for (int i = 0; i < 4; i++)
        if (i < n) atomicAdd(&g_count[d[i]], 1);
}

// ---------------------------------------------------------------------------
// Phase 2: single-block COALESCED exclusive scan.
// 98 chunks of 1024; thread t handles idx = ch*1024 + t (coalesced loads).
// Warp-shuffle inclusive scan + cross-warp smem scan; running offset carried.
// ---------------------------------------------------------------------------
#define NCHUNK ((MAX_NODES + 1023) / 1024)   // 98

__global__ __launch_bounds__(1024) void scan_kernel(int N, int E) {
    __shared__ int warpsum[32];
    int t = threadIdx.x;
    int warp = t >> 5;
    int lane = t & 31;
    int running = 0;

#pragma unroll 1
    for (int ch = 0; ch < NCHUNK; ch++) {
        int idx = ch * 1024 + t;
        int v = (idx < N) ? g_count[idx] : 0;
        // inclusive warp scan
        int s = v;
#pragma unroll
        for (int o = 1; o < 32; o <<= 1) {
            int u = __shfl_up_sync(0xFFFFFFFFu, s, o);
            if (lane >= o) s += u;
        }
        if (lane == 31) warpsum[warp] = s;
        __syncthreads();
        if (warp == 0) {
            int w = warpsum[lane];
#pragma unroll
            for (int o = 1; o < 32; o <<= 1) {
                int u = __shfl_up_sync(0xFFFFFFFFu, w, o);
                if (lane >= o) w += u;
            }
            warpsum[lane] = w;
        }
        __syncthreads();
        int woff = (warp > 0) ? warpsum[warp - 1] : 0;
        int excl = running + woff + s - v;
        if (idx < N) {
            g_rowptr[idx] = excl;
            g_cursor[idx] = excl;
        }
        running += warpsum[31];
        __syncthreads();   // protect warpsum before next chunk's writes
    }
    if (t == 0) g_rowptr[N] = E;
}

// Phase 3: fill CSR src lists, 8 edges per thread (int4 loads)
__global__ void fill_kernel(const int* __restrict__ ei32, int E) {
    int e = (blockIdx.x * blockDim.x + threadIdx.x) * 8;
    if (e >= E) return;
    int s[8], d[8];
    int n = (E - e < 8) ? (E - e) : 8;
    if (g_is64) {
        const int4* sp = reinterpret_cast<const int4*>(ei32 + 2 * e);
        const int4* dp = reinterpret_cast<const int4*>(ei32 + 2 * (E + e));
#pragma unroll
        for (int q = 0; q < 4; q++) {
            if (q * 2 < n) {
                int4 sv = __ldg(sp + q);
                int4 dv = __ldg(dp + q);
                s[q * 2] = sv.x; s[q * 2 + 1] = sv.z;
                d[q * 2] = dv.x; d[q * 2 + 1] = dv.z;
            }
        }
    } else {
        const int4* sp = reinterpret_cast<const int4*>(ei32 + e);
        const int4* dp = reinterpret_cast<const int4*>(ei32 + E + e);
#pragma unroll
        for (int q = 0; q < 2; q++) {
            if (q * 4 < n) {
                int4 sv = __ldg(sp + q);
                int4 dv = __ldg(dp + q);
                s[q * 4] = sv.x; s[q * 4 + 1] = sv.y; s[q * 4 + 2] = sv.z; s[q * 4 + 3] = sv.w;
                d[q * 4] = dv.x; d[q * 4 + 1] = dv.y; d[q * 4 + 2] = dv.z; d[q * 4 + 3] = dv.w;
            }
        }
    }
#pragma unroll
    for (int i = 0; i < 8; i++) {
        if (i < n) {
            int pos = atomicAdd(&g_cursor[d[i]], 1);
            g_csr_src[pos] = s[i];
        }
    }
}

// ---------------------------------------------------------------------------
// Phase 4: gather-aggregate (mean). One warp per dst node; lane owns 4 halves
// (uint2 = 8B). fp32 accumulation; fp16 mean written to A_cat cols 0..127.
// ---------------------------------------------------------------------------
__global__ __launch_bounds__(256) void agg_kernel(int N) {
    int w = (blockIdx.x * blockDim.x + threadIdx.x) >> 5;
    int lane = threadIdx.x & 31;
    if (w >= N) return;
    int beg = g_rowptr[w];
    int end = g_rowptr[w + 1];
    float4 acc = make_float4(0.f, 0.f, 0.f, 0.f);
    int e = beg;
    for (; e + 3 < end; e += 4) {
        int s0 = g_csr_src[e];
        int s1 = g_csr_src[e + 1];
        int s2 = g_csr_src[e + 2];
        int s3 = g_csr_src[e + 3];
        uint2 a = __ldg(reinterpret_cast<const uint2*>(g_Acat + (size_t)s0 * 256 + 128) + lane);
        uint2 b = __ldg(reinterpret_cast<const uint2*>(g_Acat + (size_t)s1 * 256 + 128) + lane);
        uint2 c = __ldg(reinterpret_cast<const uint2*>(g_Acat + (size_t)s2 * 256 + 128) + lane);
        uint2 d = __ldg(reinterpret_cast<const uint2*>(g_Acat + (size_t)s3 * 256 + 128) + lane);
#pragma unroll
        for (int q = 0; q < 4; q++) {
            uint2 v = (q == 0) ? a : (q == 1) ? b : (q == 2) ? c : d;
            float2 f0 = __half22float2(*reinterpret_cast<__half2*>(&v.x));
            float2 f1 = __half22float2(*reinterpret_cast<__half2*>(&v.y));
            acc.x += f0.x; acc.y += f0.y; acc.z += f1.x; acc.w += f1.y;
        }
    }
    for (; e < end; e++) {
        int s = g_csr_src[e];
        uint2 v = __ldg(reinterpret_cast<const uint2*>(g_Acat + (size_t)s * 256 + 128) + lane);
        float2 f0 = __half22float2(*reinterpret_cast<__half2*>(&v.x));
        float2 f1 = __half22float2(*reinterpret_cast<__half2*>(&v.y));
        acc.x += f0.x; acc.y += f0.y; acc.z += f1.x; acc.w += f1.y;
    }
    float inv = 1.0f / fmaxf((float)(end - beg), 1.0f);
    __half2 m0 = __floats2half2_rn(acc.x * inv, acc.y * inv);
    __half2 m1 = __floats2half2_rn(acc.z * inv, acc.w * inv);
    uint2 o;
    o.x = *reinterpret_cast<uint32_t*>(&m0);
    o.y = *reinterpret_cast<uint32_t*>(&m1);
    *(reinterpret_cast<uint2*>(g_Acat + (size_t)w * 256) + lane) = o;
}

// ---------------------------------------------------------------------------
// Phase 5: single-pass fp16 WMMA GEMM.
//   out[128n x 128o] = Acat[128 x 256] * Wcat^T + bias  (fp32 accum)
// CTA 128x128, 256 threads = 8 warps, warp tile 32x64 (2x4 frags).
// K chunks of 32, smem stride 40 halves. Pure uint4 staging.
// ---------------------------------------------------------------------------
#define ASTR 40

__global__ __launch_bounds__(256, 2) void gemm_fp16_kernel(
    const float* __restrict__ bl,
    float* __restrict__ out,
    int N) {
    __shared__ __align__(16) __half a_s[128 * ASTR];
    __shared__ __align__(16) __half w_s[128 * ASTR];
    __shared__ __align__(16) float bias_s[16 * 128];

    const int tid = threadIdx.x;
    const int wid = tid >> 5;
    const int node0 = blockIdx.x * 128;
    const int wr = (wid & 3) * 32;   // warp row offset
    const int wc = (wid >> 2) * 64;  // warp col offset

    // bias tile: 16 identical rows of bl[0..127]
    {
        float bv = __ldg(bl + (tid & 127));
        int r0 = tid >> 7;
#pragma unroll
        for (int r = 0; r < 16; r += 2)
            bias_s[(r + r0) * 128 + (tid & 127)] = bv;
    }
    __syncthreads();

    wmma::fragment<wmma::accumulator, 16, 16, 16, float> acc[2][4];
#pragma unroll
    for (int i = 0; i < 2; i++)
#pragma unroll
        for (int j = 0; j < 4; j++)
            wmma::load_matrix_sync(acc[i][j], &bias_s[wc + j * 16], 128, wmma::mem_row_major);

    const int row = tid >> 1;         // 0..127 (node row AND W out-col)
    const int seg = (tid & 1) * 16;   // 16-half segment of the 32-col chunk
    const int gn  = node0 + row;
    const bool va = (gn < N);

#pragma unroll 1
    for (int c = 0; c < 8; c++) {
        __syncthreads();
        // ---- stage A chunk: pure fp16 uint4 copies ----
        {
            uint4 v0, v1;
            if (va) {
                const uint4* p = reinterpret_cast<const uint4*>(g_Acat + (size_t)gn * 256 + c * 32 + seg);
                v0 = __ldg(p); v1 = __ldg(p + 1);
            } else {
                v0 = v1 = make_uint4(0, 0, 0, 0);
            }
            uint4* dst = reinterpret_cast<uint4*>(&a_s[row * ASTR + seg]);
            dst[0] = v0; dst[1] = v1;
        }
        // ---- stage W chunk ----
        {
            const uint4* p = reinterpret_cast<const uint4*>(g_Wh + row * 256 + c * 32 + seg);
            uint4* dst = reinterpret_cast<uint4*>(&w_s[row * ASTR + seg]);
            dst[0] = __ldg(p); dst[1] = __ldg(p + 1);
        }
        __syncthreads();

        // ---- compute: 2 k-steps x 2 row frags x 4 col frags ----
#pragma unroll
        for (int ks = 0; ks < 2; ks++) {
            wmma::fragment<wmma::matrix_a, 16, 16, 16, __half, wmma::row_major> af[2];
            wmma::fragment<wmma::matrix_b, 16, 16, 16, __half, wmma::col_major> bf[4];
#pragma unroll
            for (int i = 0; i < 2; i++)
                wmma::load_matrix_sync(af[i], &a_s[(wr + i * 16) * ASTR + ks * 16], ASTR);
#pragma unroll
            for (int j = 0; j < 4; j++)
                wmma::load_matrix_sync(bf[j], &w_s[(wc + j * 16) * ASTR + ks * 16], ASTR);
#pragma unroll
            for (int i = 0; i < 2; i++)
#pragma unroll
                for (int j = 0; j < 4; j++)
                    wmma::mma_sync(acc[i][j], af[i], bf[j], acc[i][j]);
        }
    }

    // ---- epilogue: direct fragment stores (bias already in acc) ----
#pragma unroll
    for (int i = 0; i < 2; i++) {
        int r0 = node0 + wr + i * 16;
        if (r0 < N) {  // N % 16 == 0 -> frag fully valid
#pragma unroll
            for (int j = 0; j < 4; j++)
                wmma::store_matrix_sync(out + (size_t)r0 * D + wc + j * 16, acc[i][j], D, wmma::mem_row_major);
        }
    }
}

// ---------------------------------------------------------------------------
extern "C" void kernel_launch(void* const* d_in, const int* in_sizes, int n_in,
                              void* d_out, int out_size) {
    const float* x    = (const float*)d_in[0];
    const int*   ei32 = (const int*)d_in[1];
    const float* Wl   = (const float*)d_in[2];
    const float* bl   = (const float*)d_in[3];
    const float* Wr   = (const float*)d_in[4];
    float*       out  = (float*)d_out;

    int N = in_sizes[0] / D;       // 100000
    int E = in_sizes[1] / 2;       // 1600000

    setup_kernel<<<SETUP_BLOCKS, 256>>>(x, Wl, Wr, ei32, N);
    hist_kernel<<<(E / 4 + 255) / 256, 256>>>(ei32, E);
    scan_kernel<<<1, 1024>>>(N, E);
    fill_kernel<<<(E / 8 + 255) / 256, 256>>>(ei32, E);
    agg_kernel<<<(N * 32 + 255) / 256, 256>>>(N);
    gemm_fp16_kernel<<<(N + 127) / 128, 256>>>(bl, out, N);
}